// round 14
// baseline (speedup 1.0000x reference)
#include <cuda_runtime.h>
#include <cuda_fp16.h>
#include <math.h>
#include <stdint.h>

// ---------------- problem constants ----------------
#define B_SZ 2
#define T_SEQ 2048
#define D_MODEL 2048
#define N_HEADS 16
#define HEAD_DIM 128
#define D_FF 5504
#define M_ROWS (B_SZ * T_SEQ)          // 4096
#define QKV_STRIDE (3 * D_MODEL)       // 6144
#define ATTN_SCALE 0.08838834764831845f

// ---------------- scratch (device globals; no runtime allocation) ----------------
__device__ __align__(1024) __half g_h   [(size_t)M_ROWS * D_MODEL];
__device__ __align__(1024) __half g_qkv [(size_t)M_ROWS * QKV_STRIDE];
__device__ __align__(1024) __half g_a   [(size_t)M_ROWS * D_MODEL];
__device__ __align__(1024) float  g_x2  [(size_t)M_ROWS * D_MODEL];
__device__ __align__(1024) __half g_h2  [(size_t)M_ROWS * D_MODEL];
__device__ __align__(1024) __half g_f2h [(size_t)M_ROWS * D_FF];
// half weights, contiguous: Wq,Wk,Wv | Wo | W1,W2 | Wout
#define O_WQ   ((size_t)0)
#define O_WK   ((size_t)D_MODEL * D_MODEL)
#define O_WV   ((size_t)2 * D_MODEL * D_MODEL)
#define O_WO   ((size_t)3 * D_MODEL * D_MODEL)
#define O_W1   ((size_t)4 * D_MODEL * D_MODEL)
#define O_W2   (O_W1 + (size_t)D_FF * D_MODEL)
#define O_WOUT (O_W2 + (size_t)D_FF * D_MODEL)
#define WBUF_TOTAL (O_WOUT + (size_t)D_FF * D_MODEL)
__device__ __align__(1024) __half g_wbuf[WBUF_TOTAL];

// ---------------- helpers ----------------
__device__ __forceinline__ uint32_t smem_u32(const void* p) {
    uint32_t a;
    asm("{ .reg .u64 t; cvta.to.shared.u64 t, %1; cvt.u32.u64 %0, t; }" : "=r"(a) : "l"(p));
    return a;
}
__device__ __forceinline__ void cp_async16(uint32_t dst, const void* src) {
    asm volatile("cp.async.cg.shared.global [%0], [%1], 16;" :: "r"(dst), "l"(src));
}
#define CP_COMMIT() asm volatile("cp.async.commit_group;" ::: "memory")
#define CP_WAIT(N)  asm volatile("cp.async.wait_group %0;" :: "n"(N) : "memory")

__device__ __forceinline__ void mma_f16(float (&d)[4], uint32_t a0, uint32_t a1,
                                        uint32_t a2, uint32_t a3, uint32_t b0, uint32_t b1) {
    asm volatile("mma.sync.aligned.m16n8k16.row.col.f32.f16.f16.f32 "
                 "{%0,%1,%2,%3}, {%4,%5,%6,%7}, {%8,%9}, {%0,%1,%2,%3};"
                 : "+f"(d[0]), "+f"(d[1]), "+f"(d[2]), "+f"(d[3])
                 : "r"(a0), "r"(a1), "r"(a2), "r"(a3), "r"(b0), "r"(b1));
}
#define LDSM4(R0,R1,R2,R3,ADDR) \
    asm volatile("ldmatrix.sync.aligned.m8n8.x4.shared.b16 {%0,%1,%2,%3}, [%4];" \
        : "=r"(R0), "=r"(R1), "=r"(R2), "=r"(R3) : "r"(ADDR))
#define LDSM4T(R0,R1,R2,R3,ADDR) \
    asm volatile("ldmatrix.sync.aligned.m8n8.x4.trans.shared.b16 {%0,%1,%2,%3}, [%4];" \
        : "=r"(R0), "=r"(R1), "=r"(R2), "=r"(R3) : "r"(ADDR))

// ---------------- shared GEMM pieces (R12-proven 3-stage) ----------------
#define GS_STRIDE_B 80
#define STAGE_A_B   10240
#define STAGE_PAIR  20480
#define GSTAGES 3
#define GEMM_SMEM_BYTES (GSTAGES * STAGE_PAIR)
#define GEMM_FF_SMEM (GEMM_SMEM_BYTES + 32768)

#define LOAD_STAGE(s) do { \
        uint32_t _base = sbase + (uint32_t)((s) % GSTAGES) * STAGE_PAIR + dOff; \
        const __half* _ap = aSrc + (size_t)(s) * 32; \
        const __half* _bp = bSrc + (size_t)(s) * 32; \
        cp_async16(_base, _ap); \
        cp_async16(_base + 64 * GS_STRIDE_B, _ap + rowJump); \
        cp_async16(_base + STAGE_A_B, _bp); \
        cp_async16(_base + STAGE_A_B + 64 * GS_STRIDE_B, _bp + rowJump); \
        CP_COMMIT(); \
    } while (0)

#define GEMM_DECLS(A, Ki)                                                              \
    const uint32_t sbase = smem_u32(smem);                                             \
    const int tid = threadIdx.x;                                                       \
    const int wid = tid >> 5, lane = tid & 31;                                         \
    const int g = lane >> 2, t = lane & 3;                                             \
    const int r8 = lane & 7, sel = lane >> 3;                                          \
    const int wm = wid & 3, wn = wid >> 2;                                             \
    const int bm = blockIdx.y * 128, bn = blockIdx.x * 128;                            \
    const int row0 = tid >> 2;                                                         \
    const int seg0 = tid & 3;                                                          \
    const __half* aSrc = (A) + (size_t)(bm + row0) * (Ki) + seg0 * 8;                  \
    const size_t rowJump = (size_t)64 * (Ki);                                          \
    const uint32_t dOff = (uint32_t)(row0 * GS_STRIDE_B + seg0 * 16);                  \
    const int nk = (Ki) / 32;                                                          \
    const uint32_t aLdOff = (uint32_t)((r8 + 8 * (sel & 1)) * GS_STRIDE_B + (sel >> 1) * 16); \
    const uint32_t bLdOff = (uint32_t)((r8 + 8 * (sel >> 1)) * GS_STRIDE_B + (sel & 1) * 16); \
    float acc[2][8][4];

#define GEMM_RESET_ACC()                                                               \
    _Pragma("unroll")                                                                  \
    for (int i = 0; i < 2; i++)                                                        \
        _Pragma("unroll")                                                              \
        for (int j = 0; j < 8; j++)                                                    \
            _Pragma("unroll")                                                          \
            for (int l = 0; l < 4; l++) acc[i][j][l] = 0.f;

#define GEMM_MAINLOOP()                                                                \
    LOAD_STAGE(0);                                                                     \
    LOAD_STAGE(1);                                                                     \
    for (int kt = 0; kt < nk; kt++) {                                                  \
        if (kt + 1 < nk) { CP_WAIT(1); } else { CP_WAIT(0); }                          \
        __syncthreads();                                                               \
        if (kt + 2 < nk) LOAD_STAGE(kt + 2);                                           \
        const uint32_t stg = sbase + (uint32_t)(kt % GSTAGES) * STAGE_PAIR;            \
        const uint32_t aBase = stg + aLdOff + (uint32_t)(wm * 32) * GS_STRIDE_B;       \
        const uint32_t bBase = stg + STAGE_A_B + bLdOff + (uint32_t)(wn * 64) * GS_STRIDE_B; \
        _Pragma("unroll")                                                              \
        for (int ks = 0; ks < 2; ks++) {                                               \
            const uint32_t kByte = (uint32_t)(ks * 32);                                \
            uint32_t af[2][4];                                                         \
            LDSM4(af[0][0], af[0][1], af[0][2], af[0][3], aBase + kByte);              \
            LDSM4(af[1][0], af[1][1], af[1][2], af[1][3],                              \
                  aBase + kByte + 16 * GS_STRIDE_B);                                   \
            uint32_t bf[4][4];                                                         \
            _Pragma("unroll")                                                          \
            for (int p = 0; p < 4; p++)                                                \
                LDSM4(bf[p][0], bf[p][1], bf[p][2], bf[p][3],                          \
                      bBase + kByte + (uint32_t)(p * 16) * GS_STRIDE_B);               \
            _Pragma("unroll")                                                          \
            for (int p = 0; p < 4; p++) {                                              \
                mma_f16(acc[0][2 * p],     af[0][0], af[0][1], af[0][2], af[0][3], bf[p][0], bf[p][1]); \
                mma_f16(acc[0][2 * p + 1], af[0][0], af[0][1], af[0][2], af[0][3], bf[p][2], bf[p][3]); \
                mma_f16(acc[1][2 * p],     af[1][0], af[1][1], af[1][2], af[1][3], bf[p][0], bf[p][1]); \
                mma_f16(acc[1][2 * p + 1], af[1][0], af[1][1], af[1][2], af[1][3], bf[p][2], bf[p][3]); \
            }                                                                          \
        }                                                                              \
    }                                                                                  \
    __syncthreads();

// ---------------- GEMM, standard epilogue (fp32+residual OR fp16) -------------
__global__ void __launch_bounds__(256, 2) gemm_f16(const __half* __restrict__ A,
                                                   const __half* __restrict__ Bw,
                                                   const float* __restrict__ addsrc,
                                                   float* __restrict__ C,
                                                   __half* __restrict__ Ch,
                                                   int Ni, int Ki) {
    extern __shared__ char smem[];
    GEMM_DECLS(A, Ki)
    const __half* bSrc = Bw + (size_t)(bn + row0) * Ki + seg0 * 8;
    GEMM_RESET_ACC()
    GEMM_MAINLOOP()

#pragma unroll
    for (int mt = 0; mt < 2; mt++) {
#pragma unroll
        for (int nt = 0; nt < 8; nt++) {
            int r = bm + wm * 32 + mt * 16 + g;
            int c = bn + wn * 64 + nt * 8 + t * 2;
            size_t i0 = (size_t)r * Ni + c;
            size_t i1 = i0 + (size_t)8 * Ni;
            if (Ch) {
                __half2 h0 = __floats2half2_rn(acc[mt][nt][0], acc[mt][nt][1]);
                __half2 h1 = __floats2half2_rn(acc[mt][nt][2], acc[mt][nt][3]);
                *(__half2*)(Ch + i0) = h0;
                *(__half2*)(Ch + i1) = h1;
            } else {
                float2 o0 = make_float2(acc[mt][nt][0], acc[mt][nt][1]);
                float2 o1 = make_float2(acc[mt][nt][2], acc[mt][nt][3]);
                if (addsrc) {
                    float2 s0 = *(const float2*)(addsrc + i0);
                    float2 s1 = *(const float2*)(addsrc + i1);
                    o0.x += s0.x; o0.y += s0.y;
                    o1.x += s1.x; o1.y += s1.y;
                }
                *(float2*)(C + i0) = o0;
                *(float2*)(C + i1) = o1;
            }
        }
    }
}

// ---------------- merged FF GEMM: f2h = silu(A@W1^T) * (A@W2^T), two passes ----
__global__ void __launch_bounds__(256, 2) gemm_f16_ff(const __half* __restrict__ A,
                                                      const __half* __restrict__ W1w,
                                                      const __half* __restrict__ W2w,
                                                      __half* __restrict__ Ch,
                                                      int Ni, int Ki) {
    extern __shared__ char smem[];
    GEMM_DECLS(A, Ki)
    uint32_t* gsm = (uint32_t*)(smem + GEMM_SMEM_BYTES);
    const __half* bSrc;

    for (int pass = 0; pass < 2; pass++) {
        const __half* Bw = pass ? W2w : W1w;
        bSrc = Bw + (size_t)(bn + row0) * Ki + seg0 * 8;
        GEMM_RESET_ACC()
        GEMM_MAINLOOP()
        if (pass == 0) {
#pragma unroll
            for (int mt = 0; mt < 2; mt++) {
#pragma unroll
                for (int nt = 0; nt < 8; nt++) {
                    int slot = (mt * 8 + nt) * 2;
                    float z0 = acc[mt][nt][0], z1 = acc[mt][nt][1];
                    float z2 = acc[mt][nt][2], z3 = acc[mt][nt][3];
                    __half2 h01 = __floats2half2_rn(z0 / (1.f + expf(-z0)),
                                                    z1 / (1.f + expf(-z1)));
                    __half2 h23 = __floats2half2_rn(z2 / (1.f + expf(-z2)),
                                                    z3 / (1.f + expf(-z3)));
                    gsm[slot * 256 + tid]       = *(uint32_t*)&h01;
                    gsm[(slot + 1) * 256 + tid] = *(uint32_t*)&h23;
                }
            }
        }
    }

#pragma unroll
    for (int mt = 0; mt < 2; mt++) {
#pragma unroll
        for (int nt = 0; nt < 8; nt++) {
            int r = bm + wm * 32 + mt * 16 + g;
            int c = bn + wn * 64 + nt * 8 + t * 2;
            size_t i0 = (size_t)r * Ni + c;
            size_t i1 = i0 + (size_t)8 * Ni;
            int slot = (mt * 8 + nt) * 2;
            uint32_t u01 = gsm[slot * 256 + tid];
            uint32_t u23 = gsm[(slot + 1) * 256 + tid];
            float2 g01 = __half22float2(*(__half2*)&u01);
            float2 g23 = __half22float2(*(__half2*)&u23);
            __half2 h0 = __floats2half2_rn(g01.x * acc[mt][nt][0], g01.y * acc[mt][nt][1]);
            __half2 h1 = __floats2half2_rn(g23.x * acc[mt][nt][2], g23.y * acc[mt][nt][3]);
            *(__half2*)(Ch + i0) = h0;
            *(__half2*)(Ch + i1) = h1;
        }
    }
}

// ---------------- fused fp32 -> fp16 weight conversion (MLP=4) ----------------
#define SEG_DD (D_MODEL * D_MODEL / 4)
#define SEG_FD (D_FF * D_MODEL / 4)
#define CONV_TOTAL (4 * SEG_DD + 3 * SEG_FD)

__global__ void __launch_bounds__(256) tohalf_all_k(const float4* __restrict__ Wq,
                                                    const float4* __restrict__ Wk,
                                                    const float4* __restrict__ Wv,
                                                    const float4* __restrict__ Wo,
                                                    const float4* __restrict__ W1,
                                                    const float4* __restrict__ W2,
                                                    const float4* __restrict__ Wout,
                                                    __half2* __restrict__ out) {
    int i0 = blockIdx.x * 1024 + threadIdx.x;
#pragma unroll
    for (int u = 0; u < 4; u++) {
        int i = i0 + u * 256;
        if (i >= CONV_TOTAL) break;
        const float4* src;
        int off;
        if (i < 4 * SEG_DD) {
            int seg = i / SEG_DD;
            off = i - seg * SEG_DD;
            src = (seg == 0) ? Wq : (seg == 1) ? Wk : (seg == 2) ? Wv : Wo;
        } else {
            int j = i - 4 * SEG_DD;
            int seg = j / SEG_FD;
            off = j - seg * SEG_FD;
            src = (seg == 0) ? W1 : (seg == 1) ? W2 : Wout;
        }
        float4 v = src[off];
        out[(size_t)i * 2]     = __floats2half2_rn(v.x, v.y);
        out[(size_t)i * 2 + 1] = __floats2half2_rn(v.z, v.w);
    }
}

// ---------------- RMSNorm: one block per row, float4 loads, fp16 out ----------
__global__ void __launch_bounds__(256) rmsnorm_k(const float* __restrict__ x,
                                                 const float* __restrict__ w,
                                                 __half* __restrict__ out, int Dm) {
    int row = blockIdx.x;
    const float4* xr4 = (const float4*)(x + (size_t)row * Dm);
    const float4* w4  = (const float4*)w;
    const int n4 = Dm / 4;
    float ss = 0.f;
    for (int i = threadIdx.x; i < n4; i += 256) {
        float4 v = xr4[i];
        ss += v.x * v.x + v.y * v.y + v.z * v.z + v.w * v.w;
    }
    __shared__ float red[256];
    red[threadIdx.x] = ss;
    __syncthreads();
    for (int s = 128; s > 0; s >>= 1) {
        if (threadIdx.x < s) red[threadIdx.x] += red[threadIdx.x + s];
        __syncthreads();
    }
    float rms = sqrtf(red[0] / (float)Dm);
    float inv = 1.0f / (rms + 1e-8f);
    __half2* orow = (__half2*)(out + (size_t)row * Dm);
    for (int i = threadIdx.x; i < n4; i += 256) {
        float4 v = xr4[i];
        float4 g4 = w4[i];
        orow[i * 2]     = __floats2half2_rn(g4.x * v.x * inv, g4.y * v.y * inv);
        orow[i * 2 + 1] = __floats2half2_rn(g4.z * v.z * inv, g4.w * v.w * inv);
    }
}

// ---------------- RoPE on packed QKV (in-place, fp16, half2-vectorized) -------
__global__ void __launch_bounds__(256) rope_qkv_k(__half* __restrict__ qkv,
                                                  const float* __restrict__ cs,
                                                  const float* __restrict__ sn) {
    int idx = blockIdx.x * 256 + threadIdx.x;
    int dp = (idx & 31) * 2;
    int head = (idx >> 5) & (N_HEADS - 1);
    int row = idx >> 9;
    if (row >= M_ROWS) return;
    int t = row & (T_SEQ - 1);
    float2 c1 = *(const float2*)(cs + t * HEAD_DIM + dp);
    float2 s1 = *(const float2*)(sn + t * HEAD_DIM + dp);
    float2 c2 = *(const float2*)(cs + t * HEAD_DIM + dp + 64);
    float2 s2 = *(const float2*)(sn + t * HEAD_DIM + dp + 64);
    size_t base = (size_t)row * QKV_STRIDE + head * HEAD_DIM;
    __half2* q0 = (__half2*)(qkv + base + dp);
    __half2* q1 = (__half2*)(qkv + base + dp + 64);
    __half2* k0 = (__half2*)(qkv + base + D_MODEL + dp);
    __half2* k1 = (__half2*)(qkv + base + D_MODEL + dp + 64);
    float2 qa = __half22float2(*q0), qb = __half22float2(*q1);
    *q0 = __floats2half2_rn(qa.x * c1.x - qb.x * s1.x, qa.y * c1.y - qb.y * s1.y);
    *q1 = __floats2half2_rn(qb.x * c2.x + qa.x * s2.x, qb.y * c2.y + qa.y * s2.y);
    float2 ka = __half22float2(*k0), kb = __half22float2(*k1);
    *k0 = __floats2half2_rn(ka.x * c1.x - kb.x * s1.x, ka.y * c1.y - kb.y * s1.y);
    *k1 = __floats2half2_rn(kb.x * c2.x + ka.x * s2.x, kb.y * c2.y + ka.y * s2.y);
}

// ---------------- Flash attention, 128-row Q tiles, 8 warps ------------------
#define FROW_B 272
#define FQBUF_B (128 * FROW_B)              // 34816
#define FKVBUF_B (64 * FROW_B)              // 17408
#define FLASH_SMEM_BYTES (FQBUF_B + 4 * FKVBUF_B)  // 104448

__global__ void __launch_bounds__(256) flash_mma_k(const __half* __restrict__ QKV,
                                                   __half* __restrict__ O) {
    extern __shared__ char fsm[];
    const uint32_t sQ  = smem_u32(fsm);
    const uint32_t sK0 = sQ + FQBUF_B, sV0 = sK0 + FKVBUF_B;
    const uint32_t sK1 = sV0 + FKVBUF_B, sV1 = sK1 + FKVBUF_B;

    const int qt2 = (int)(gridDim.x - 1 - blockIdx.x);  // LPT order
    const int h = blockIdx.y, b = blockIdx.z;
    const int tid = threadIdx.x;
    const int w = tid >> 5, lane = tid & 31;
    const int g = lane >> 2, t = lane & 3;
    const int r8 = lane & 7, sel = lane >> 3;

    const size_t seq0 = (size_t)b * T_SEQ;
    const size_t col0 = (size_t)h * HEAD_DIM;
    const __half* Q = QKV + col0;
    const __half* K = QKV + col0 + D_MODEL;
    const __half* V = QKV + col0 + 2 * D_MODEL;

    const int lrow = tid >> 4;     // 0..15
    const int lc   = tid & 15;
    const size_t gOff = (size_t)lrow * QKV_STRIDE + lc * 8;
    const uint32_t sOff = (uint32_t)(lrow * FROW_B + lc * 16);

// K/V tile: 64 rows, 256 threads -> 4 iterations of 16-row steps
#define FLOADKV(SBASE, GPTR) do { \
        const __half* _g = (GPTR) + gOff; \
        uint32_t _s = (SBASE) + sOff; \
        _Pragma("unroll") \
        for (int _i = 0; _i < 4; _i++) { \
            cp_async16(_s, _g); \
            _s += 16 * FROW_B; _g += (size_t)16 * QKV_STRIDE; \
        } \
    } while (0)
// Q tile: 128 rows -> 8 iterations
#define FLOADQ(SBASE, GPTR) do { \
        const __half* _g = (GPTR) + gOff; \
        uint32_t _s = (SBASE) + sOff; \
        _Pragma("unroll") \
        for (int _i = 0; _i < 8; _i++) { \
            cp_async16(_s, _g); \
            _s += 16 * FROW_B; _g += (size_t)16 * QKV_STRIDE; \
        } \
    } while (0)

    FLOADQ(sQ, Q + (seq0 + (size_t)qt2 * 128) * QKV_STRIDE);
    FLOADKV(sK0, K + seq0 * QKV_STRIDE);
    FLOADKV(sV0, V + seq0 * QKV_STRIDE);
    CP_COMMIT();
    CP_WAIT(0);
    __syncthreads();

    uint32_t qa[8][4];
    {
        uint32_t qbase = sQ + (uint32_t)((16 * w + r8 + 8 * (sel & 1)) * FROW_B + (sel >> 1) * 16);
#pragma unroll
        for (int u = 0; u < 8; u++)
            LDSM4(qa[u][0], qa[u][1], qa[u][2], qa[u][3], qbase + u * 32);
    }

    const uint32_t koff = (uint32_t)((r8 + 8 * (sel >> 1)) * FROW_B + (sel & 1) * 16);
    const uint32_t voff = (uint32_t)((8 * (sel & 1) + r8) * FROW_B + (sel >> 1) * 16);

    float oacc[16][4];
#pragma unroll
    for (int j = 0; j < 16; j++) { oacc[j][0] = 0; oacc[j][1] = 0; oacc[j][2] = 0; oacc[j][3] = 0; }
    float mA = -1e30f, mB = -1e30f, lA = 0.f, lB = 0.f;

    const int rowA = qt2 * 128 + 16 * w + g;
    const int rowB = rowA + 8;
    const float CEXP = ATTN_SCALE * 1.4426950408889634f;
    const int nkt = 2 * qt2 + 2;

    for (int kt = 0; kt < nkt; kt++) {
        const uint32_t sK = (kt & 1) ? sK1 : sK0;
        const uint32_t sV = (kt & 1) ? sV1 : sV0;
        const bool more = (kt + 1) < nkt;
        if (more) {
            const uint32_t nK = (kt & 1) ? sK0 : sK1;
            const uint32_t nV = (kt & 1) ? sV0 : sV1;
            FLOADKV(nK, K + (seq0 + (size_t)(kt + 1) * 64) * QKV_STRIDE);
            FLOADKV(nV, V + (seq0 + (size_t)(kt + 1) * 64) * QKV_STRIDE);
            CP_COMMIT();
        }
        if (kt > 0) {
            if (more) { CP_WAIT(1); } else { CP_WAIT(0); }
            __syncthreads();
        }

        float sacc[8][4];
#pragma unroll
        for (int j = 0; j < 8; j++) { sacc[j][0] = 0; sacc[j][1] = 0; sacc[j][2] = 0; sacc[j][3] = 0; }
#pragma unroll
        for (int u = 0; u < 8; u++) {
#pragma unroll
            for (int jp = 0; jp < 4; jp++) {
                uint32_t k0, k1, k2, k3;
                LDSM4(k0, k1, k2, k3, sK + koff + jp * (16 * FROW_B) + u * 32);
                mma_f16(sacc[2 * jp],     qa[u][0], qa[u][1], qa[u][2], qa[u][3], k0, k1);
                mma_f16(sacc[2 * jp + 1], qa[u][0], qa[u][1], qa[u][2], qa[u][3], k2, k3);
            }
        }

        if (kt >= 2 * qt2) {
#pragma unroll
            for (int j = 0; j < 8; j++) {
                int c0 = kt * 64 + 8 * j + 2 * t;
                if (c0     > rowA) sacc[j][0] = -1e30f;
                if (c0 + 1 > rowA) sacc[j][1] = -1e30f;
                if (c0     > rowB) sacc[j][2] = -1e30f;
                if (c0 + 1 > rowB) sacc[j][3] = -1e30f;
            }
        }

        float mxA = -1e30f, mxB = -1e30f;
#pragma unroll
        for (int j = 0; j < 8; j++) {
            mxA = fmaxf(mxA, fmaxf(sacc[j][0], sacc[j][1]));
            mxB = fmaxf(mxB, fmaxf(sacc[j][2], sacc[j][3]));
        }
        mxA = fmaxf(mxA, __shfl_xor_sync(0xffffffffu, mxA, 1));
        mxA = fmaxf(mxA, __shfl_xor_sync(0xffffffffu, mxA, 2));
        mxB = fmaxf(mxB, __shfl_xor_sync(0xffffffffu, mxB, 1));
        mxB = fmaxf(mxB, __shfl_xor_sync(0xffffffffu, mxB, 2));
        float mnA = fmaxf(mA, mxA), mnB = fmaxf(mB, mxB);
        float aA = exp2f((mA - mnA) * CEXP), aB = exp2f((mB - mnB) * CEXP);
        mA = mnA; mB = mnB;

        uint32_t ph[8][2];
        float sA = 0.f, sB = 0.f;
#pragma unroll
        for (int j = 0; j < 8; j++) {
            float p0 = exp2f((sacc[j][0] - mnA) * CEXP);
            float p1 = exp2f((sacc[j][1] - mnA) * CEXP);
            float p2 = exp2f((sacc[j][2] - mnB) * CEXP);
            float p3 = exp2f((sacc[j][3] - mnB) * CEXP);
            __half2 h01 = __floats2half2_rn(p0, p1);
            __half2 h23 = __floats2half2_rn(p2, p3);
            ph[j][0] = *(uint32_t*)&h01;
            ph[j][1] = *(uint32_t*)&h23;
            float2 f01 = __half22float2(h01);
            float2 f23 = __half22float2(h23);
            sA += f01.x + f01.y;
            sB += f23.x + f23.y;
        }
        sA += __shfl_xor_sync(0xffffffffu, sA, 1);
        sA += __shfl_xor_sync(0xffffffffu, sA, 2);
        sB += __shfl_xor_sync(0xffffffffu, sB, 1);
        sB += __shfl_xor_sync(0xffffffffu, sB, 2);
        lA = lA * aA + sA;
        lB = lB * aB + sB;

#pragma unroll
        for (int j = 0; j < 16; j++) {
            oacc[j][0] *= aA; oacc[j][1] *= aA;
            oacc[j][2] *= aB; oacc[j][3] *= aB;
        }

#pragma unroll
        for (int uk = 0; uk < 4; uk++) {
            uint32_t a0 = ph[2 * uk][0], a1 = ph[2 * uk][1];
            uint32_t a2 = ph[2 * uk + 1][0], a3 = ph[2 * uk + 1][1];
#pragma unroll
            for (int jp = 0; jp < 8; jp++) {
                uint32_t v0, v1, v2, v3;
                LDSM4T(v0, v1, v2, v3, sV + voff + uk * (16 * FROW_B) + jp * 32);
                mma_f16(oacc[2 * jp],     a0, a1, a2, a3, v0, v1);
                mma_f16(oacc[2 * jp + 1], a0, a1, a2, a3, v2, v3);
            }
        }
        __syncthreads();
    }
#undef FLOADKV
#undef FLOADQ

    float iA = 1.f / lA, iB = 1.f / lB;
    __half* orA = O + (seq0 + rowA) * D_MODEL + col0 + 2 * t;
    __half* orB = O + (seq0 + rowB) * D_MODEL + col0 + 2 * t;
#pragma unroll
    for (int j = 0; j < 16; j++) {
        __half2 hA = __floats2half2_rn(oacc[j][0] * iA, oacc[j][1] * iA);
        __half2 hB = __floats2half2_rn(oacc[j][2] * iB, oacc[j][3] * iB);
        *(__half2*)(orA + 8 * j) = hA;
        *(__half2*)(orB + 8 * j) = hB;
    }
}

// ---------------- launch ----------------
extern "C" void kernel_launch(void* const* d_in, const int* in_sizes, int n_in,
                              void* d_out, int out_size) {
    const float* x    = (const float*)d_in[0];
    const float* cs   = (const float*)d_in[1];
    const float* sn   = (const float*)d_in[2];
    const float* g1   = (const float*)d_in[4];
    const float* g2   = (const float*)d_in[5];
    const float* Wq   = (const float*)d_in[6];
    const float* Wk   = (const float*)d_in[7];
    const float* Wv   = (const float*)d_in[8];
    const float* Wo   = (const float*)d_in[9];
    const float* W1   = (const float*)d_in[10];
    const float* W2   = (const float*)d_in[11];
    const float* Wout = (const float*)d_in[12];
    float* out = (float*)d_out;

    __half *ph, *pqkv, *pa, *ph2, *pf2h, *pw;
    float *px2;
    cudaGetSymbolAddress((void**)&ph,   g_h);
    cudaGetSymbolAddress((void**)&pqkv, g_qkv);
    cudaGetSymbolAddress((void**)&pa,   g_a);
    cudaGetSymbolAddress((void**)&px2,  g_x2);
    cudaGetSymbolAddress((void**)&ph2,  g_h2);
    cudaGetSymbolAddress((void**)&pf2h, g_f2h);
    cudaGetSymbolAddress((void**)&pw,   g_wbuf);

    cudaFuncSetAttribute(gemm_f16, cudaFuncAttributeMaxDynamicSharedMemorySize,
                         GEMM_SMEM_BYTES);
    cudaFuncSetAttribute(gemm_f16_ff, cudaFuncAttributeMaxDynamicSharedMemorySize,
                         GEMM_FF_SMEM);
    cudaFuncSetAttribute(flash_mma_k, cudaFuncAttributeMaxDynamicSharedMemorySize,
                         FLASH_SMEM_BYTES);

    // 0) fused weight conversion (1 launch, MLP=4)
    tohalf_all_k<<<(CONV_TOTAL + 1023) / 1024, 256>>>(
        (const float4*)Wq, (const float4*)Wk, (const float4*)Wv, (const float4*)Wo,
        (const float4*)W1, (const float4*)W2, (const float4*)Wout, (__half2*)pw);

    // 1) h = rmsnorm(x, g1)  (fp16 out)
    rmsnorm_k<<<M_ROWS, 256>>>(x, g1, ph, D_MODEL);

    // 2) fused QKV projection: [M,6144] = h @ [Wq;Wk;Wv]^T
    dim3 gqkv(QKV_STRIDE / 128, M_ROWS / 128);
    gemm_f16<<<gqkv, 256, GEMM_SMEM_BYTES>>>(ph, pw + O_WQ, nullptr, nullptr, pqkv,
                                             QKV_STRIDE, D_MODEL);

    // 3) RoPE on packed QKV (half2-vectorized)
    rope_qkv_k<<<(M_ROWS * N_HEADS * 32) / 256, 256>>>(pqkv, cs, sn);

    // 4) causal flash attention (128-row Q tiles, 8 warps) -> fp16
    dim3 gattn(T_SEQ / 128, N_HEADS, B_SZ);
    flash_mma_k<<<gattn, 256, FLASH_SMEM_BYTES>>>(pqkv, pa);

    // 5) x2 = x + attn @ Wo^T
    dim3 gproj(D_MODEL / 128, M_ROWS / 128);
    gemm_f16<<<gproj, 256, GEMM_SMEM_BYTES>>>(pa, pw + O_WO, x, px2, nullptr,
                                              D_MODEL, D_MODEL);

    // 6) h2 = rmsnorm(x2, g2)
    rmsnorm_k<<<M_ROWS, 256>>>(px2, g2, ph2, D_MODEL);

    // 7) merged FF: f2h = silu(h2@W1^T) * (h2@W2^T)
    dim3 gff(D_FF / 128, M_ROWS / 128);
    gemm_f16_ff<<<gff, 256, GEMM_FF_SMEM>>>(ph2, pw + O_W1, pw + O_W2, pf2h,
                                            D_FF, D_MODEL);

    // 8) out = x2 + f2h @ Wout^T
    gemm_f16<<<gproj, 256, GEMM_SMEM_BYTES>>>(pf2h, pw + O_WOUT, px2, out, nullptr,
                                              D_MODEL, D_FF);
}

// round 15
// speedup vs baseline: 1.0548x; 1.0548x over previous
#include <cuda_runtime.h>
#include <cuda_fp16.h>
#include <math.h>
#include <stdint.h>

// ---------------- problem constants ----------------
#define B_SZ 2
#define T_SEQ 2048
#define D_MODEL 2048
#define N_HEADS 16
#define HEAD_DIM 128
#define D_FF 5504
#define M_ROWS (B_SZ * T_SEQ)          // 4096
#define QKV_STRIDE (3 * D_MODEL)       // 6144
#define ATTN_SCALE 0.08838834764831845f

// ---------------- scratch (device globals; no runtime allocation) ----------------
__device__ __align__(1024) __half g_h   [(size_t)M_ROWS * D_MODEL];
__device__ __align__(1024) __half g_qkv [(size_t)M_ROWS * QKV_STRIDE];
__device__ __align__(1024) __half g_a   [(size_t)M_ROWS * D_MODEL];
__device__ __align__(1024) float  g_x2  [(size_t)M_ROWS * D_MODEL];
__device__ __align__(1024) __half g_h2  [(size_t)M_ROWS * D_MODEL];
__device__ __align__(1024) __half g_f2h [(size_t)M_ROWS * D_FF];
// half weights, contiguous: Wq,Wk,Wv | Wo | W1,W2 | Wout
#define O_WQ   ((size_t)0)
#define O_WK   ((size_t)D_MODEL * D_MODEL)
#define O_WV   ((size_t)2 * D_MODEL * D_MODEL)
#define O_WO   ((size_t)3 * D_MODEL * D_MODEL)
#define O_W1   ((size_t)4 * D_MODEL * D_MODEL)
#define O_W2   (O_W1 + (size_t)D_FF * D_MODEL)
#define O_WOUT (O_W2 + (size_t)D_FF * D_MODEL)
#define WBUF_TOTAL (O_WOUT + (size_t)D_FF * D_MODEL)
__device__ __align__(1024) __half g_wbuf[WBUF_TOTAL];

// ---------------- helpers ----------------
__device__ __forceinline__ uint32_t smem_u32(const void* p) {
    uint32_t a;
    asm("{ .reg .u64 t; cvta.to.shared.u64 t, %1; cvt.u32.u64 %0, t; }" : "=r"(a) : "l"(p));
    return a;
}
__device__ __forceinline__ void cp_async16(uint32_t dst, const void* src) {
    asm volatile("cp.async.cg.shared.global [%0], [%1], 16;" :: "r"(dst), "l"(src));
}
#define CP_COMMIT() asm volatile("cp.async.commit_group;" ::: "memory")
#define CP_WAIT(N)  asm volatile("cp.async.wait_group %0;" :: "n"(N) : "memory")

__device__ __forceinline__ void mma_f16(float (&d)[4], uint32_t a0, uint32_t a1,
                                        uint32_t a2, uint32_t a3, uint32_t b0, uint32_t b1) {
    asm volatile("mma.sync.aligned.m16n8k16.row.col.f32.f16.f16.f32 "
                 "{%0,%1,%2,%3}, {%4,%5,%6,%7}, {%8,%9}, {%0,%1,%2,%3};"
                 : "+f"(d[0]), "+f"(d[1]), "+f"(d[2]), "+f"(d[3])
                 : "r"(a0), "r"(a1), "r"(a2), "r"(a3), "r"(b0), "r"(b1));
}
#define LDSM4(R0,R1,R2,R3,ADDR) \
    asm volatile("ldmatrix.sync.aligned.m8n8.x4.shared.b16 {%0,%1,%2,%3}, [%4];" \
        : "=r"(R0), "=r"(R1), "=r"(R2), "=r"(R3) : "r"(ADDR))
#define LDSM4T(R0,R1,R2,R3,ADDR) \
    asm volatile("ldmatrix.sync.aligned.m8n8.x4.trans.shared.b16 {%0,%1,%2,%3}, [%4];" \
        : "=r"(R0), "=r"(R1), "=r"(R2), "=r"(R3) : "r"(ADDR))

// =========== standard GEMM: BK=64, 3-stage, single-sync (this round) ==========
#define GS64_STRIDE_B 144
#define STAGE64_A_B   18432            // 128 rows * 144 B
#define STAGE64_PAIR  36864
#define GEMM64_SMEM   (3 * STAGE64_PAIR)   // 110592

__global__ void __launch_bounds__(256, 2) gemm_f16(const __half* __restrict__ A,
                                                   const __half* __restrict__ Bw,
                                                   const float* __restrict__ addsrc,
                                                   float* __restrict__ C,
                                                   __half* __restrict__ Ch,
                                                   int Ni, int Ki) {
    extern __shared__ char smem[];
    const uint32_t sbase = smem_u32(smem);
    const int tid = threadIdx.x;
    const int wid = tid >> 5, lane = tid & 31;
    const int g = lane >> 2, t = lane & 3;
    const int r8 = lane & 7, sel = lane >> 3;
    const int wm = wid & 3, wn = wid >> 2;
    const int bm = blockIdx.y * 128, bn = blockIdx.x * 128;

    float acc[2][8][4];
#pragma unroll
    for (int i = 0; i < 2; i++)
#pragma unroll
        for (int j = 0; j < 8; j++)
#pragma unroll
            for (int l = 0; l < 4; l++) acc[i][j][l] = 0.f;

    const int row0 = tid >> 3;          // 0..31
    const int seg0 = tid & 7;           // 0..7 (16B segments of a 128B row)
    const __half* aSrc = A  + (size_t)(bm + row0) * Ki + seg0 * 8;
    const __half* bSrc = Bw + (size_t)(bn + row0) * Ki + seg0 * 8;
    const size_t rowJump = (size_t)32 * Ki;
    const uint32_t dOff = (uint32_t)(row0 * GS64_STRIDE_B + seg0 * 16);
    const int nk = Ki / 64;

#define LOAD_STAGE64(s) do { \
        uint32_t _bA = sbase + (uint32_t)((s) % 3) * STAGE64_PAIR + dOff; \
        uint32_t _bB = _bA + STAGE64_A_B; \
        const __half* _ap = aSrc + (size_t)(s) * 64; \
        const __half* _bp = bSrc + (size_t)(s) * 64; \
        _Pragma("unroll") \
        for (int _i = 0; _i < 4; _i++) { \
            cp_async16(_bA, _ap); \
            cp_async16(_bB, _bp); \
            _bA += 32 * GS64_STRIDE_B; _bB += 32 * GS64_STRIDE_B; \
            _ap += rowJump; _bp += rowJump; \
        } \
        CP_COMMIT(); \
    } while (0)

    LOAD_STAGE64(0);
    LOAD_STAGE64(1);

    const uint32_t aLdOff = (uint32_t)((r8 + 8 * (sel & 1)) * GS64_STRIDE_B + (sel >> 1) * 16);
    const uint32_t bLdOff = (uint32_t)((r8 + 8 * (sel >> 1)) * GS64_STRIDE_B + (sel & 1) * 16);

    for (int kt = 0; kt < nk; kt++) {
        if (kt + 1 < nk) { CP_WAIT(1); } else { CP_WAIT(0); }
        __syncthreads();
        if (kt + 2 < nk) LOAD_STAGE64(kt + 2);

        const uint32_t stg = sbase + (uint32_t)(kt % 3) * STAGE64_PAIR;
        const uint32_t aBase = stg + aLdOff + (uint32_t)(wm * 32) * GS64_STRIDE_B;
        const uint32_t bBase = stg + STAGE64_A_B + bLdOff + (uint32_t)(wn * 64) * GS64_STRIDE_B;

#pragma unroll
        for (int ks = 0; ks < 4; ks++) {
            const uint32_t kByte = (uint32_t)(ks * 32);
            uint32_t af[2][4];
            LDSM4(af[0][0], af[0][1], af[0][2], af[0][3], aBase + kByte);
            LDSM4(af[1][0], af[1][1], af[1][2], af[1][3],
                  aBase + kByte + 16 * GS64_STRIDE_B);
            uint32_t bf[4][4];
#pragma unroll
            for (int p = 0; p < 4; p++)
                LDSM4(bf[p][0], bf[p][1], bf[p][2], bf[p][3],
                      bBase + kByte + (uint32_t)(p * 16) * GS64_STRIDE_B);
#pragma unroll
            for (int p = 0; p < 4; p++) {
                mma_f16(acc[0][2 * p],     af[0][0], af[0][1], af[0][2], af[0][3], bf[p][0], bf[p][1]);
                mma_f16(acc[0][2 * p + 1], af[0][0], af[0][1], af[0][2], af[0][3], bf[p][2], bf[p][3]);
                mma_f16(acc[1][2 * p],     af[1][0], af[1][1], af[1][2], af[1][3], bf[p][0], bf[p][1]);
                mma_f16(acc[1][2 * p + 1], af[1][0], af[1][1], af[1][2], af[1][3], bf[p][2], bf[p][3]);
            }
        }
    }
    __syncthreads();
#undef LOAD_STAGE64

#pragma unroll
    for (int mt = 0; mt < 2; mt++) {
#pragma unroll
        for (int nt = 0; nt < 8; nt++) {
            int r = bm + wm * 32 + mt * 16 + g;
            int c = bn + wn * 64 + nt * 8 + t * 2;
            size_t i0 = (size_t)r * Ni + c;
            size_t i1 = i0 + (size_t)8 * Ni;
            if (Ch) {
                __half2 h0 = __floats2half2_rn(acc[mt][nt][0], acc[mt][nt][1]);
                __half2 h1 = __floats2half2_rn(acc[mt][nt][2], acc[mt][nt][3]);
                *(__half2*)(Ch + i0) = h0;
                *(__half2*)(Ch + i1) = h1;
            } else {
                float2 o0 = make_float2(acc[mt][nt][0], acc[mt][nt][1]);
                float2 o1 = make_float2(acc[mt][nt][2], acc[mt][nt][3]);
                if (addsrc) {
                    float2 s0 = *(const float2*)(addsrc + i0);
                    float2 s1 = *(const float2*)(addsrc + i1);
                    o0.x += s0.x; o0.y += s0.y;
                    o1.x += s1.x; o1.y += s1.y;
                }
                *(float2*)(C + i0) = o0;
                *(float2*)(C + i1) = o1;
            }
        }
    }
}

// =========== FF GEMM: R12-proven BK=32, 3-stage + gate slab ====================
#define GS_STRIDE_B 80
#define STAGE_A_B   10240
#define STAGE_PAIR  20480
#define GSTAGES 3
#define GEMM_SMEM_BYTES (GSTAGES * STAGE_PAIR)
#define GEMM_FF_SMEM (GEMM_SMEM_BYTES + 32768)

#define LOAD_STAGE(s) do { \
        uint32_t _base = sbase + (uint32_t)((s) % GSTAGES) * STAGE_PAIR + dOff; \
        const __half* _ap = aSrc + (size_t)(s) * 32; \
        const __half* _bp = bSrc + (size_t)(s) * 32; \
        cp_async16(_base, _ap); \
        cp_async16(_base + 64 * GS_STRIDE_B, _ap + rowJump); \
        cp_async16(_base + STAGE_A_B, _bp); \
        cp_async16(_base + STAGE_A_B + 64 * GS_STRIDE_B, _bp + rowJump); \
        CP_COMMIT(); \
    } while (0)

__global__ void __launch_bounds__(256, 2) gemm_f16_ff(const __half* __restrict__ A,
                                                      const __half* __restrict__ W1w,
                                                      const __half* __restrict__ W2w,
                                                      __half* __restrict__ Ch,
                                                      int Ni, int Ki) {
    extern __shared__ char smem[];
    const uint32_t sbase = smem_u32(smem);
    const int tid = threadIdx.x;
    const int wid = tid >> 5, lane = tid & 31;
    const int g = lane >> 2, t = lane & 3;
    const int r8 = lane & 7, sel = lane >> 3;
    const int wm = wid & 3, wn = wid >> 2;
    const int bm = blockIdx.y * 128, bn = blockIdx.x * 128;
    const int row0 = tid >> 2;
    const int seg0 = tid & 3;
    const __half* aSrc = A + (size_t)(bm + row0) * Ki + seg0 * 8;
    const size_t rowJump = (size_t)64 * Ki;
    const uint32_t dOff = (uint32_t)(row0 * GS_STRIDE_B + seg0 * 16);
    const int nk = Ki / 32;
    const uint32_t aLdOff = (uint32_t)((r8 + 8 * (sel & 1)) * GS_STRIDE_B + (sel >> 1) * 16);
    const uint32_t bLdOff = (uint32_t)((r8 + 8 * (sel >> 1)) * GS_STRIDE_B + (sel & 1) * 16);
    float acc[2][8][4];
    uint32_t* gsm = (uint32_t*)(smem + GEMM_SMEM_BYTES);
    const __half* bSrc;

    for (int pass = 0; pass < 2; pass++) {
        const __half* Bw = pass ? W2w : W1w;
        bSrc = Bw + (size_t)(bn + row0) * Ki + seg0 * 8;
#pragma unroll
        for (int i = 0; i < 2; i++)
#pragma unroll
            for (int j = 0; j < 8; j++)
#pragma unroll
                for (int l = 0; l < 4; l++) acc[i][j][l] = 0.f;

        LOAD_STAGE(0);
        LOAD_STAGE(1);
        for (int kt = 0; kt < nk; kt++) {
            if (kt + 1 < nk) { CP_WAIT(1); } else { CP_WAIT(0); }
            __syncthreads();
            if (kt + 2 < nk) LOAD_STAGE(kt + 2);
            const uint32_t stg = sbase + (uint32_t)(kt % GSTAGES) * STAGE_PAIR;
            const uint32_t aBase = stg + aLdOff + (uint32_t)(wm * 32) * GS_STRIDE_B;
            const uint32_t bBase = stg + STAGE_A_B + bLdOff + (uint32_t)(wn * 64) * GS_STRIDE_B;
#pragma unroll
            for (int ks = 0; ks < 2; ks++) {
                const uint32_t kByte = (uint32_t)(ks * 32);
                uint32_t af[2][4];
                LDSM4(af[0][0], af[0][1], af[0][2], af[0][3], aBase + kByte);
                LDSM4(af[1][0], af[1][1], af[1][2], af[1][3],
                      aBase + kByte + 16 * GS_STRIDE_B);
                uint32_t bf[4][4];
#pragma unroll
                for (int p = 0; p < 4; p++)
                    LDSM4(bf[p][0], bf[p][1], bf[p][2], bf[p][3],
                          bBase + kByte + (uint32_t)(p * 16) * GS_STRIDE_B);
#pragma unroll
                for (int p = 0; p < 4; p++) {
                    mma_f16(acc[0][2 * p],     af[0][0], af[0][1], af[0][2], af[0][3], bf[p][0], bf[p][1]);
                    mma_f16(acc[0][2 * p + 1], af[0][0], af[0][1], af[0][2], af[0][3], bf[p][2], bf[p][3]);
                    mma_f16(acc[1][2 * p],     af[1][0], af[1][1], af[1][2], af[1][3], bf[p][0], bf[p][1]);
                    mma_f16(acc[1][2 * p + 1], af[1][0], af[1][1], af[1][2], af[1][3], bf[p][2], bf[p][3]);
                }
            }
        }
        __syncthreads();

        if (pass == 0) {
#pragma unroll
            for (int mt = 0; mt < 2; mt++) {
#pragma unroll
                for (int nt = 0; nt < 8; nt++) {
                    int slot = (mt * 8 + nt) * 2;
                    float z0 = acc[mt][nt][0], z1 = acc[mt][nt][1];
                    float z2 = acc[mt][nt][2], z3 = acc[mt][nt][3];
                    __half2 h01 = __floats2half2_rn(z0 / (1.f + expf(-z0)),
                                                    z1 / (1.f + expf(-z1)));
                    __half2 h23 = __floats2half2_rn(z2 / (1.f + expf(-z2)),
                                                    z3 / (1.f + expf(-z3)));
                    gsm[slot * 256 + tid]       = *(uint32_t*)&h01;
                    gsm[(slot + 1) * 256 + tid] = *(uint32_t*)&h23;
                }
            }
        }
    }

#pragma unroll
    for (int mt = 0; mt < 2; mt++) {
#pragma unroll
        for (int nt = 0; nt < 8; nt++) {
            int r = bm + wm * 32 + mt * 16 + g;
            int c = bn + wn * 64 + nt * 8 + t * 2;
            size_t i0 = (size_t)r * Ni + c;
            size_t i1 = i0 + (size_t)8 * Ni;
            int slot = (mt * 8 + nt) * 2;
            uint32_t u01 = gsm[slot * 256 + tid];
            uint32_t u23 = gsm[(slot + 1) * 256 + tid];
            float2 g01 = __half22float2(*(__half2*)&u01);
            float2 g23 = __half22float2(*(__half2*)&u23);
            __half2 h0 = __floats2half2_rn(g01.x * acc[mt][nt][0], g01.y * acc[mt][nt][1]);
            __half2 h1 = __floats2half2_rn(g23.x * acc[mt][nt][2], g23.y * acc[mt][nt][3]);
            *(__half2*)(Ch + i0) = h0;
            *(__half2*)(Ch + i1) = h1;
        }
    }
}

// ---------------- fused fp32 -> fp16 weight conversion (MLP=4) ----------------
#define SEG_DD (D_MODEL * D_MODEL / 4)
#define SEG_FD (D_FF * D_MODEL / 4)
#define CONV_TOTAL (4 * SEG_DD + 3 * SEG_FD)

__global__ void __launch_bounds__(256) tohalf_all_k(const float4* __restrict__ Wq,
                                                    const float4* __restrict__ Wk,
                                                    const float4* __restrict__ Wv,
                                                    const float4* __restrict__ Wo,
                                                    const float4* __restrict__ W1,
                                                    const float4* __restrict__ W2,
                                                    const float4* __restrict__ Wout,
                                                    __half2* __restrict__ out) {
    int i0 = blockIdx.x * 1024 + threadIdx.x;
#pragma unroll
    for (int u = 0; u < 4; u++) {
        int i = i0 + u * 256;
        if (i >= CONV_TOTAL) break;
        const float4* src;
        int off;
        if (i < 4 * SEG_DD) {
            int seg = i / SEG_DD;
            off = i - seg * SEG_DD;
            src = (seg == 0) ? Wq : (seg == 1) ? Wk : (seg == 2) ? Wv : Wo;
        } else {
            int j = i - 4 * SEG_DD;
            int seg = j / SEG_FD;
            off = j - seg * SEG_FD;
            src = (seg == 0) ? W1 : (seg == 1) ? W2 : Wout;
        }
        float4 v = src[off];
        out[(size_t)i * 2]     = __floats2half2_rn(v.x, v.y);
        out[(size_t)i * 2 + 1] = __floats2half2_rn(v.z, v.w);
    }
}

// ---------------- RMSNorm: one block per row, float4 loads, fp16 out ----------
__global__ void __launch_bounds__(256) rmsnorm_k(const float* __restrict__ x,
                                                 const float* __restrict__ w,
                                                 __half* __restrict__ out, int Dm) {
    int row = blockIdx.x;
    const float4* xr4 = (const float4*)(x + (size_t)row * Dm);
    const float4* w4  = (const float4*)w;
    const int n4 = Dm / 4;
    float ss = 0.f;
    for (int i = threadIdx.x; i < n4; i += 256) {
        float4 v = xr4[i];
        ss += v.x * v.x + v.y * v.y + v.z * v.z + v.w * v.w;
    }
    __shared__ float red[256];
    red[threadIdx.x] = ss;
    __syncthreads();
    for (int s = 128; s > 0; s >>= 1) {
        if (threadIdx.x < s) red[threadIdx.x] += red[threadIdx.x + s];
        __syncthreads();
    }
    float rms = sqrtf(red[0] / (float)Dm);
    float inv = 1.0f / (rms + 1e-8f);
    __half2* orow = (__half2*)(out + (size_t)row * Dm);
    for (int i = threadIdx.x; i < n4; i += 256) {
        float4 v = xr4[i];
        float4 g4 = w4[i];
        orow[i * 2]     = __floats2half2_rn(g4.x * v.x * inv, g4.y * v.y * inv);
        orow[i * 2 + 1] = __floats2half2_rn(g4.z * v.z * inv, g4.w * v.w * inv);
    }
}

// ---------------- RoPE on packed QKV (in-place, fp16, half2-vectorized) -------
__global__ void __launch_bounds__(256) rope_qkv_k(__half* __restrict__ qkv,
                                                  const float* __restrict__ cs,
                                                  const float* __restrict__ sn) {
    int idx = blockIdx.x * 256 + threadIdx.x;
    int dp = (idx & 31) * 2;
    int head = (idx >> 5) & (N_HEADS - 1);
    int row = idx >> 9;
    if (row >= M_ROWS) return;
    int t = row & (T_SEQ - 1);
    float2 c1 = *(const float2*)(cs + t * HEAD_DIM + dp);
    float2 s1 = *(const float2*)(sn + t * HEAD_DIM + dp);
    float2 c2 = *(const float2*)(cs + t * HEAD_DIM + dp + 64);
    float2 s2 = *(const float2*)(sn + t * HEAD_DIM + dp + 64);
    size_t base = (size_t)row * QKV_STRIDE + head * HEAD_DIM;
    __half2* q0 = (__half2*)(qkv + base + dp);
    __half2* q1 = (__half2*)(qkv + base + dp + 64);
    __half2* k0 = (__half2*)(qkv + base + D_MODEL + dp);
    __half2* k1 = (__half2*)(qkv + base + D_MODEL + dp + 64);
    float2 qa = __half22float2(*q0), qb = __half22float2(*q1);
    *q0 = __floats2half2_rn(qa.x * c1.x - qb.x * s1.x, qa.y * c1.y - qb.y * s1.y);
    *q1 = __floats2half2_rn(qb.x * c2.x + qa.x * s2.x, qb.y * c2.y + qa.y * s2.y);
    float2 ka = __half22float2(*k0), kb = __half22float2(*k1);
    *k0 = __floats2half2_rn(ka.x * c1.x - kb.x * s1.x, ka.y * c1.y - kb.y * s1.y);
    *k1 = __floats2half2_rn(kb.x * c2.x + ka.x * s2.x, kb.y * c2.y + ka.y * s2.y);
}

// ---------------- Flash attention (R12-proven, 64-row Q tiles, 4 warps) -------
#define FROW_B 272
#define FBUF_B (64 * FROW_B)
#define FLASH_SMEM_BYTES (5 * FBUF_B)

__global__ void __launch_bounds__(128) flash_mma_k(const __half* __restrict__ QKV,
                                                   __half* __restrict__ O) {
    extern __shared__ char fsm[];
    const uint32_t sQ  = smem_u32(fsm);
    const uint32_t sK0 = sQ + FBUF_B, sV0 = sQ + 2 * FBUF_B;
    const uint32_t sK1 = sQ + 3 * FBUF_B, sV1 = sQ + 4 * FBUF_B;

    const int qt = (int)(gridDim.x - 1 - blockIdx.x);  // LPT order
    const int h = blockIdx.y, b = blockIdx.z;
    const int tid = threadIdx.x;
    const int w = tid >> 5, lane = tid & 31;
    const int g = lane >> 2, t = lane & 3;
    const int r8 = lane & 7, sel = lane >> 3;

    const size_t seq0 = (size_t)b * T_SEQ;
    const size_t col0 = (size_t)h * HEAD_DIM;
    const __half* Q = QKV + col0;
    const __half* K = QKV + col0 + D_MODEL;
    const __half* V = QKV + col0 + 2 * D_MODEL;

    const int lrow = tid >> 4;
    const int lc   = tid & 15;
    const size_t gOff = (size_t)lrow * QKV_STRIDE + lc * 8;
    const uint32_t sOff = (uint32_t)(lrow * FROW_B + lc * 16);

#define FLOAD(SBASE, GPTR) do { \
        const __half* _g = (GPTR) + gOff; \
        uint32_t _s = (SBASE) + sOff; \
        _Pragma("unroll") \
        for (int _i = 0; _i < 8; _i++) { \
            cp_async16(_s, _g); \
            _s += 8 * FROW_B; _g += (size_t)8 * QKV_STRIDE; \
        } \
    } while (0)

    FLOAD(sQ, Q + (seq0 + (size_t)qt * 64) * QKV_STRIDE);
    FLOAD(sK0, K + seq0 * QKV_STRIDE);
    FLOAD(sV0, V + seq0 * QKV_STRIDE);
    CP_COMMIT();
    CP_WAIT(0);
    __syncthreads();

    uint32_t qa[8][4];
    {
        uint32_t qbase = sQ + (uint32_t)((16 * w + r8 + 8 * (sel & 1)) * FROW_B + (sel >> 1) * 16);
#pragma unroll
        for (int u = 0; u < 8; u++)
            LDSM4(qa[u][0], qa[u][1], qa[u][2], qa[u][3], qbase + u * 32);
    }

    const uint32_t koff = (uint32_t)((r8 + 8 * (sel >> 1)) * FROW_B + (sel & 1) * 16);
    const uint32_t voff = (uint32_t)((8 * (sel & 1) + r8) * FROW_B + (sel >> 1) * 16);

    float oacc[16][4];
#pragma unroll
    for (int j = 0; j < 16; j++) { oacc[j][0] = 0; oacc[j][1] = 0; oacc[j][2] = 0; oacc[j][3] = 0; }
    float mA = -1e30f, mB = -1e30f, lA = 0.f, lB = 0.f;

    const int rowA = qt * 64 + 16 * w + g;
    const int rowB = rowA + 8;
    const float CEXP = ATTN_SCALE * 1.4426950408889634f;

    for (int kt = 0; kt <= qt; kt++) {
        const uint32_t sK = (kt & 1) ? sK1 : sK0;
        const uint32_t sV = (kt & 1) ? sV1 : sV0;
        const bool more = (kt + 1) <= qt;
        if (more) {
            const uint32_t nK = (kt & 1) ? sK0 : sK1;
            const uint32_t nV = (kt & 1) ? sV0 : sV1;
            FLOAD(nK, K + (seq0 + (size_t)(kt + 1) * 64) * QKV_STRIDE);
            FLOAD(nV, V + (seq0 + (size_t)(kt + 1) * 64) * QKV_STRIDE);
            CP_COMMIT();
        }
        if (kt > 0) {
            if (more) { CP_WAIT(1); } else { CP_WAIT(0); }
            __syncthreads();
        }

        float sacc[8][4];
#pragma unroll
        for (int j = 0; j < 8; j++) { sacc[j][0] = 0; sacc[j][1] = 0; sacc[j][2] = 0; sacc[j][3] = 0; }
#pragma unroll
        for (int u = 0; u < 8; u++) {
#pragma unroll
            for (int jp = 0; jp < 4; jp++) {
                uint32_t k0, k1, k2, k3;
                LDSM4(k0, k1, k2, k3, sK + koff + jp * (16 * FROW_B) + u * 32);
                mma_f16(sacc[2 * jp],     qa[u][0], qa[u][1], qa[u][2], qa[u][3], k0, k1);
                mma_f16(sacc[2 * jp + 1], qa[u][0], qa[u][1], qa[u][2], qa[u][3], k2, k3);
            }
        }

        if (kt == qt) {
#pragma unroll
            for (int j = 0; j < 8; j++) {
                int c0 = kt * 64 + 8 * j + 2 * t;
                if (c0     > rowA) sacc[j][0] = -1e30f;
                if (c0 + 1 > rowA) sacc[j][1] = -1e30f;
                if (c0     > rowB) sacc[j][2] = -1e30f;
                if (c0 + 1 > rowB) sacc[j][3] = -1e30f;
            }
        }

        float mxA = -1e30f, mxB = -1e30f;
#pragma unroll
        for (int j = 0; j < 8; j++) {
            mxA = fmaxf(mxA, fmaxf(sacc[j][0], sacc[j][1]));
            mxB = fmaxf(mxB, fmaxf(sacc[j][2], sacc[j][3]));
        }
        mxA = fmaxf(mxA, __shfl_xor_sync(0xffffffffu, mxA, 1));
        mxA = fmaxf(mxA, __shfl_xor_sync(0xffffffffu, mxA, 2));
        mxB = fmaxf(mxB, __shfl_xor_sync(0xffffffffu, mxB, 1));
        mxB = fmaxf(mxB, __shfl_xor_sync(0xffffffffu, mxB, 2));
        float mnA = fmaxf(mA, mxA), mnB = fmaxf(mB, mxB);
        float aA = exp2f((mA - mnA) * CEXP), aB = exp2f((mB - mnB) * CEXP);
        mA = mnA; mB = mnB;

        uint32_t ph[8][2];
        float sA = 0.f, sB = 0.f;
#pragma unroll
        for (int j = 0; j < 8; j++) {
            float p0 = exp2f((sacc[j][0] - mnA) * CEXP);
            float p1 = exp2f((sacc[j][1] - mnA) * CEXP);
            float p2 = exp2f((sacc[j][2] - mnB) * CEXP);
            float p3 = exp2f((sacc[j][3] - mnB) * CEXP);
            __half2 h01 = __floats2half2_rn(p0, p1);
            __half2 h23 = __floats2half2_rn(p2, p3);
            ph[j][0] = *(uint32_t*)&h01;
            ph[j][1] = *(uint32_t*)&h23;
            float2 f01 = __half22float2(h01);
            float2 f23 = __half22float2(h23);
            sA += f01.x + f01.y;
            sB += f23.x + f23.y;
        }
        sA += __shfl_xor_sync(0xffffffffu, sA, 1);
        sA += __shfl_xor_sync(0xffffffffu, sA, 2);
        sB += __shfl_xor_sync(0xffffffffu, sB, 1);
        sB += __shfl_xor_sync(0xffffffffu, sB, 2);
        lA = lA * aA + sA;
        lB = lB * aB + sB;

#pragma unroll
        for (int j = 0; j < 16; j++) {
            oacc[j][0] *= aA; oacc[j][1] *= aA;
            oacc[j][2] *= aB; oacc[j][3] *= aB;
        }

#pragma unroll
        for (int uk = 0; uk < 4; uk++) {
            uint32_t a0 = ph[2 * uk][0], a1 = ph[2 * uk][1];
            uint32_t a2 = ph[2 * uk + 1][0], a3 = ph[2 * uk + 1][1];
#pragma unroll
            for (int jp = 0; jp < 8; jp++) {
                uint32_t v0, v1, v2, v3;
                LDSM4T(v0, v1, v2, v3, sV + voff + uk * (16 * FROW_B) + jp * 32);
                mma_f16(oacc[2 * jp],     a0, a1, a2, a3, v0, v1);
                mma_f16(oacc[2 * jp + 1], a0, a1, a2, a3, v2, v3);
            }
        }
        __syncthreads();
    }
#undef FLOAD

    float iA = 1.f / lA, iB = 1.f / lB;
    __half* orA = O + (seq0 + rowA) * D_MODEL + col0 + 2 * t;
    __half* orB = O + (seq0 + rowB) * D_MODEL + col0 + 2 * t;
#pragma unroll
    for (int j = 0; j < 16; j++) {
        __half2 hA = __floats2half2_rn(oacc[j][0] * iA, oacc[j][1] * iA);
        __half2 hB = __floats2half2_rn(oacc[j][2] * iB, oacc[j][3] * iB);
        *(__half2*)(orA + 8 * j) = hA;
        *(__half2*)(orB + 8 * j) = hB;
    }
}

// ---------------- launch ----------------
extern "C" void kernel_launch(void* const* d_in, const int* in_sizes, int n_in,
                              void* d_out, int out_size) {
    const float* x    = (const float*)d_in[0];
    const float* cs   = (const float*)d_in[1];
    const float* sn   = (const float*)d_in[2];
    const float* g1   = (const float*)d_in[4];
    const float* g2   = (const float*)d_in[5];
    const float* Wq   = (const float*)d_in[6];
    const float* Wk   = (const float*)d_in[7];
    const float* Wv   = (const float*)d_in[8];
    const float* Wo   = (const float*)d_in[9];
    const float* W1   = (const float*)d_in[10];
    const float* W2   = (const float*)d_in[11];
    const float* Wout = (const float*)d_in[12];
    float* out = (float*)d_out;

    __half *ph, *pqkv, *pa, *ph2, *pf2h, *pw;
    float *px2;
    cudaGetSymbolAddress((void**)&ph,   g_h);
    cudaGetSymbolAddress((void**)&pqkv, g_qkv);
    cudaGetSymbolAddress((void**)&pa,   g_a);
    cudaGetSymbolAddress((void**)&px2,  g_x2);
    cudaGetSymbolAddress((void**)&ph2,  g_h2);
    cudaGetSymbolAddress((void**)&pf2h, g_f2h);
    cudaGetSymbolAddress((void**)&pw,   g_wbuf);

    cudaFuncSetAttribute(gemm_f16, cudaFuncAttributeMaxDynamicSharedMemorySize,
                         GEMM64_SMEM);
    cudaFuncSetAttribute(gemm_f16_ff, cudaFuncAttributeMaxDynamicSharedMemorySize,
                         GEMM_FF_SMEM);
    cudaFuncSetAttribute(flash_mma_k, cudaFuncAttributeMaxDynamicSharedMemorySize,
                         FLASH_SMEM_BYTES);

    // 0) fused weight conversion (1 launch, MLP=4)
    tohalf_all_k<<<(CONV_TOTAL + 1023) / 1024, 256>>>(
        (const float4*)Wq, (const float4*)Wk, (const float4*)Wv, (const float4*)Wo,
        (const float4*)W1, (const float4*)W2, (const float4*)Wout, (__half2*)pw);

    // 1) h = rmsnorm(x, g1)  (fp16 out)
    rmsnorm_k<<<M_ROWS, 256>>>(x, g1, ph, D_MODEL);

    // 2) fused QKV projection: [M,6144] = h @ [Wq;Wk;Wv]^T  (BK=64)
    dim3 gqkv(QKV_STRIDE / 128, M_ROWS / 128);
    gemm_f16<<<gqkv, 256, GEMM64_SMEM>>>(ph, pw + O_WQ, nullptr, nullptr, pqkv,
                                         QKV_STRIDE, D_MODEL);

    // 3) RoPE on packed QKV (half2-vectorized)
    rope_qkv_k<<<(M_ROWS * N_HEADS * 32) / 256, 256>>>(pqkv, cs, sn);

    // 4) causal flash attention (64-row Q tiles, R12-proven) -> fp16
    dim3 gattn(T_SEQ / 64, N_HEADS, B_SZ);
    flash_mma_k<<<gattn, 128, FLASH_SMEM_BYTES>>>(pqkv, pa);

    // 5) x2 = x + attn @ Wo^T  (BK=64)
    dim3 gproj(D_MODEL / 128, M_ROWS / 128);
    gemm_f16<<<gproj, 256, GEMM64_SMEM>>>(pa, pw + O_WO, x, px2, nullptr,
                                          D_MODEL, D_MODEL);

    // 6) h2 = rmsnorm(x2, g2)
    rmsnorm_k<<<M_ROWS, 256>>>(px2, g2, ph2, D_MODEL);

    // 7) merged FF: f2h = silu(h2@W1^T) * (h2@W2^T)  (BK=32 + gate slab)
    dim3 gff(D_FF / 128, M_ROWS / 128);
    gemm_f16_ff<<<gff, 256, GEMM_FF_SMEM>>>(ph2, pw + O_W1, pw + O_W2, pf2h,
                                            D_FF, D_MODEL);

    // 8) out = x2 + f2h @ Wout^T  (BK=64, Ki=5504 -> 86 tiles)
    gemm_f16<<<gproj, 256, GEMM64_SMEM>>>(pf2h, pw + O_WOUT, px2, out, nullptr,
                                          D_MODEL, D_FF);
}

// round 16
// speedup vs baseline: 1.0950x; 1.0382x over previous
#include <cuda_runtime.h>
#include <cuda_fp16.h>
#include <math.h>
#include <stdint.h>

// ---------------- problem constants ----------------
#define B_SZ 2
#define T_SEQ 2048
#define D_MODEL 2048
#define N_HEADS 16
#define HEAD_DIM 128
#define D_FF 5504
#define M_ROWS (B_SZ * T_SEQ)          // 4096
#define QKV_STRIDE (3 * D_MODEL)       // 6144
#define ATTN_SCALE 0.08838834764831845f

// ---------------- scratch (device globals; no runtime allocation) ----------------
__device__ __align__(1024) __half g_h   [(size_t)M_ROWS * D_MODEL];
__device__ __align__(1024) __half g_qkv [(size_t)M_ROWS * QKV_STRIDE];
__device__ __align__(1024) __half g_a   [(size_t)M_ROWS * D_MODEL];
__device__ __align__(1024) float  g_x2  [(size_t)M_ROWS * D_MODEL];
__device__ __align__(1024) __half g_h2  [(size_t)M_ROWS * D_MODEL];
__device__ __align__(1024) __half g_f2h [(size_t)M_ROWS * D_FF];
// half weights, contiguous: Wq,Wk,Wv | Wo | W1,W2 | Wout
#define O_WQ   ((size_t)0)
#define O_WK   ((size_t)D_MODEL * D_MODEL)
#define O_WV   ((size_t)2 * D_MODEL * D_MODEL)
#define O_WO   ((size_t)3 * D_MODEL * D_MODEL)
#define O_W1   ((size_t)4 * D_MODEL * D_MODEL)
#define O_W2   (O_W1 + (size_t)D_FF * D_MODEL)
#define O_WOUT (O_W2 + (size_t)D_FF * D_MODEL)
#define WBUF_TOTAL (O_WOUT + (size_t)D_FF * D_MODEL)
__device__ __align__(1024) __half g_wbuf[WBUF_TOTAL];

// ---------------- helpers ----------------
__device__ __forceinline__ uint32_t smem_u32(const void* p) {
    uint32_t a;
    asm("{ .reg .u64 t; cvta.to.shared.u64 t, %1; cvt.u32.u64 %0, t; }" : "=r"(a) : "l"(p));
    return a;
}
__device__ __forceinline__ void cp_async16(uint32_t dst, const void* src) {
    asm volatile("cp.async.cg.shared.global [%0], [%1], 16;" :: "r"(dst), "l"(src));
}
#define CP_COMMIT() asm volatile("cp.async.commit_group;" ::: "memory")
#define CP_WAIT(N)  asm volatile("cp.async.wait_group %0;" :: "n"(N) : "memory")

__device__ __forceinline__ void mma_f16(float (&d)[4], uint32_t a0, uint32_t a1,
                                        uint32_t a2, uint32_t a3, uint32_t b0, uint32_t b1) {
    asm volatile("mma.sync.aligned.m16n8k16.row.col.f32.f16.f16.f32 "
                 "{%0,%1,%2,%3}, {%4,%5,%6,%7}, {%8,%9}, {%0,%1,%2,%3};"
                 : "+f"(d[0]), "+f"(d[1]), "+f"(d[2]), "+f"(d[3])
                 : "r"(a0), "r"(a1), "r"(a2), "r"(a3), "r"(b0), "r"(b1));
}
#define LDSM4(R0,R1,R2,R3,ADDR) \
    asm volatile("ldmatrix.sync.aligned.m8n8.x4.shared.b16 {%0,%1,%2,%3}, [%4];" \
        : "=r"(R0), "=r"(R1), "=r"(R2), "=r"(R3) : "r"(ADDR))
#define LDSM4T(R0,R1,R2,R3,ADDR) \
    asm volatile("ldmatrix.sync.aligned.m8n8.x4.trans.shared.b16 {%0,%1,%2,%3}, [%4];" \
        : "=r"(R0), "=r"(R1), "=r"(R2), "=r"(R3) : "r"(ADDR))

// =========== BK=64 GEMM core (R15-proven) =====================================
#define GS64_STRIDE_B 144
#define STAGE64_A_B   18432            // 128 rows * 144 B
#define STAGE64_PAIR  36864
#define GEMM64_SMEM   (3 * STAGE64_PAIR)   // 110592

#define GEMM64_DECLS(A, Ki)                                                            \
    const uint32_t sbase = smem_u32(smem);                                             \
    const int tid = threadIdx.x;                                                       \
    const int wid = tid >> 5, lane = tid & 31;                                         \
    const int g = lane >> 2, t = lane & 3;                                             \
    const int r8 = lane & 7, sel = lane >> 3;                                          \
    const int wm = wid & 3, wn = wid >> 2;                                             \
    const int bm = blockIdx.y * 128, bn = blockIdx.x * 128;                            \
    const int row0 = tid >> 3;                                                         \
    const int seg0 = tid & 7;                                                          \
    const __half* aSrc = (A) + (size_t)(bm + row0) * (Ki) + seg0 * 8;                  \
    const size_t rowJump = (size_t)32 * (Ki);                                          \
    const uint32_t dOff = (uint32_t)(row0 * GS64_STRIDE_B + seg0 * 16);                \
    const int nk = (Ki) / 64;                                                          \
    const uint32_t aLdOff = (uint32_t)((r8 + 8 * (sel & 1)) * GS64_STRIDE_B + (sel >> 1) * 16); \
    const uint32_t bLdOff = (uint32_t)((r8 + 8 * (sel >> 1)) * GS64_STRIDE_B + (sel & 1) * 16); \
    float acc[2][8][4];

#define GEMM64_RESET_ACC()                                                             \
    _Pragma("unroll")                                                                  \
    for (int i = 0; i < 2; i++)                                                        \
        _Pragma("unroll")                                                              \
        for (int j = 0; j < 8; j++)                                                    \
            _Pragma("unroll")                                                          \
            for (int l = 0; l < 4; l++) acc[i][j][l] = 0.f;

#define LOAD_STAGE64(s) do { \
        uint32_t _bA = sbase + (uint32_t)((s) % 3) * STAGE64_PAIR + dOff; \
        uint32_t _bB = _bA + STAGE64_A_B; \
        const __half* _ap = aSrc + (size_t)(s) * 64; \
        const __half* _bp = bSrc + (size_t)(s) * 64; \
        _Pragma("unroll") \
        for (int _i = 0; _i < 4; _i++) { \
            cp_async16(_bA, _ap); \
            cp_async16(_bB, _bp); \
            _bA += 32 * GS64_STRIDE_B; _bB += 32 * GS64_STRIDE_B; \
            _ap += rowJump; _bp += rowJump; \
        } \
        CP_COMMIT(); \
    } while (0)

#define GEMM64_MAINLOOP()                                                              \
    LOAD_STAGE64(0);                                                                   \
    LOAD_STAGE64(1);                                                                   \
    for (int kt = 0; kt < nk; kt++) {                                                  \
        if (kt + 1 < nk) { CP_WAIT(1); } else { CP_WAIT(0); }                          \
        __syncthreads();                                                               \
        if (kt + 2 < nk) LOAD_STAGE64(kt + 2);                                         \
        const uint32_t stg = sbase + (uint32_t)(kt % 3) * STAGE64_PAIR;                \
        const uint32_t aBase = stg + aLdOff + (uint32_t)(wm * 32) * GS64_STRIDE_B;     \
        const uint32_t bBase = stg + STAGE64_A_B + bLdOff + (uint32_t)(wn * 64) * GS64_STRIDE_B; \
        _Pragma("unroll")                                                              \
        for (int ks = 0; ks < 4; ks++) {                                               \
            const uint32_t kByte = (uint32_t)(ks * 32);                                \
            uint32_t af[2][4];                                                         \
            LDSM4(af[0][0], af[0][1], af[0][2], af[0][3], aBase + kByte);              \
            LDSM4(af[1][0], af[1][1], af[1][2], af[1][3],                              \
                  aBase + kByte + 16 * GS64_STRIDE_B);                                 \
            uint32_t bf[4][4];                                                         \
            _Pragma("unroll")                                                          \
            for (int p = 0; p < 4; p++)                                                \
                LDSM4(bf[p][0], bf[p][1], bf[p][2], bf[p][3],                          \
                      bBase + kByte + (uint32_t)(p * 16) * GS64_STRIDE_B);             \
            _Pragma("unroll")                                                          \
            for (int p = 0; p < 4; p++) {                                              \
                mma_f16(acc[0][2 * p],     af[0][0], af[0][1], af[0][2], af[0][3], bf[p][0], bf[p][1]); \
                mma_f16(acc[0][2 * p + 1], af[0][0], af[0][1], af[0][2], af[0][3], bf[p][2], bf[p][3]); \
                mma_f16(acc[1][2 * p],     af[1][0], af[1][1], af[1][2], af[1][3], bf[p][0], bf[p][1]); \
                mma_f16(acc[1][2 * p + 1], af[1][0], af[1][1], af[1][2], af[1][3], bf[p][2], bf[p][3]); \
            }                                                                          \
        }                                                                              \
    }                                                                                  \
    __syncthreads();

// ---------------- standard GEMM (fp32+residual OR fp16 epilogue) --------------
__global__ void __launch_bounds__(256, 2) gemm_f16(const __half* __restrict__ A,
                                                   const __half* __restrict__ Bw,
                                                   const float* __restrict__ addsrc,
                                                   float* __restrict__ C,
                                                   __half* __restrict__ Ch,
                                                   int Ni, int Ki) {
    extern __shared__ char smem[];
    GEMM64_DECLS(A, Ki)
    const __half* bSrc = Bw + (size_t)(bn + row0) * Ki + seg0 * 8;
    GEMM64_RESET_ACC()
    GEMM64_MAINLOOP()

#pragma unroll
    for (int mt = 0; mt < 2; mt++) {
#pragma unroll
        for (int nt = 0; nt < 8; nt++) {
            int r = bm + wm * 32 + mt * 16 + g;
            int c = bn + wn * 64 + nt * 8 + t * 2;
            size_t i0 = (size_t)r * Ni + c;
            size_t i1 = i0 + (size_t)8 * Ni;
            if (Ch) {
                __half2 h0 = __floats2half2_rn(acc[mt][nt][0], acc[mt][nt][1]);
                __half2 h1 = __floats2half2_rn(acc[mt][nt][2], acc[mt][nt][3]);
                *(__half2*)(Ch + i0) = h0;
                *(__half2*)(Ch + i1) = h1;
            } else {
                float2 o0 = make_float2(acc[mt][nt][0], acc[mt][nt][1]);
                float2 o1 = make_float2(acc[mt][nt][2], acc[mt][nt][3]);
                if (addsrc) {
                    float2 s0 = *(const float2*)(addsrc + i0);
                    float2 s1 = *(const float2*)(addsrc + i1);
                    o0.x += s0.x; o0.y += s0.y;
                    o1.x += s1.x; o1.y += s1.y;
                }
                *(float2*)(C + i0) = o0;
                *(float2*)(C + i1) = o1;
            }
        }
    }
}

// ---------------- merged FF GEMM, BK=64, gate staged through Ch ---------------
// pass 0: Ch = silu(A@W1^T) (fp16). pass 1: Ch = Ch * (A@W2^T).
// Same thread writes & re-reads its own Ch addresses -> no sync needed.
__global__ void __launch_bounds__(256, 2) gemm_f16_ff(const __half* __restrict__ A,
                                                      const __half* __restrict__ W1w,
                                                      const __half* __restrict__ W2w,
                                                      __half* __restrict__ Ch,
                                                      int Ni, int Ki) {
    extern __shared__ char smem[];
    GEMM64_DECLS(A, Ki)
    const __half* bSrc;

    for (int pass = 0; pass < 2; pass++) {
        const __half* Bw = pass ? W2w : W1w;
        bSrc = Bw + (size_t)(bn + row0) * Ki + seg0 * 8;
        GEMM64_RESET_ACC()
        GEMM64_MAINLOOP()

#pragma unroll
        for (int mt = 0; mt < 2; mt++) {
#pragma unroll
            for (int nt = 0; nt < 8; nt++) {
                int r = bm + wm * 32 + mt * 16 + g;
                int c = bn + wn * 64 + nt * 8 + t * 2;
                size_t i0 = (size_t)r * Ni + c;
                size_t i1 = i0 + (size_t)8 * Ni;
                if (pass == 0) {
                    float z0 = acc[mt][nt][0], z1 = acc[mt][nt][1];
                    float z2 = acc[mt][nt][2], z3 = acc[mt][nt][3];
                    __half2 h0 = __floats2half2_rn(z0 / (1.f + expf(-z0)),
                                                   z1 / (1.f + expf(-z1)));
                    __half2 h1 = __floats2half2_rn(z2 / (1.f + expf(-z2)),
                                                   z3 / (1.f + expf(-z3)));
                    *(__half2*)(Ch + i0) = h0;
                    *(__half2*)(Ch + i1) = h1;
                } else {
                    float2 g0 = __half22float2(*(const __half2*)(Ch + i0));
                    float2 g1 = __half22float2(*(const __half2*)(Ch + i1));
                    __half2 h0 = __floats2half2_rn(g0.x * acc[mt][nt][0],
                                                   g0.y * acc[mt][nt][1]);
                    __half2 h1 = __floats2half2_rn(g1.x * acc[mt][nt][2],
                                                   g1.y * acc[mt][nt][3]);
                    *(__half2*)(Ch + i0) = h0;
                    *(__half2*)(Ch + i1) = h1;
                }
            }
        }
    }
}

// ---------------- fused fp32 -> fp16 weight conversion (MLP=4) ----------------
#define SEG_DD (D_MODEL * D_MODEL / 4)
#define SEG_FD (D_FF * D_MODEL / 4)
#define CONV_TOTAL (4 * SEG_DD + 3 * SEG_FD)

__global__ void __launch_bounds__(256) tohalf_all_k(const float4* __restrict__ Wq,
                                                    const float4* __restrict__ Wk,
                                                    const float4* __restrict__ Wv,
                                                    const float4* __restrict__ Wo,
                                                    const float4* __restrict__ W1,
                                                    const float4* __restrict__ W2,
                                                    const float4* __restrict__ Wout,
                                                    __half2* __restrict__ out) {
    int i0 = blockIdx.x * 1024 + threadIdx.x;
#pragma unroll
    for (int u = 0; u < 4; u++) {
        int i = i0 + u * 256;
        if (i >= CONV_TOTAL) break;
        const float4* src;
        int off;
        if (i < 4 * SEG_DD) {
            int seg = i / SEG_DD;
            off = i - seg * SEG_DD;
            src = (seg == 0) ? Wq : (seg == 1) ? Wk : (seg == 2) ? Wv : Wo;
        } else {
            int j = i - 4 * SEG_DD;
            int seg = j / SEG_FD;
            off = j - seg * SEG_FD;
            src = (seg == 0) ? W1 : (seg == 1) ? W2 : Wout;
        }
        float4 v = src[off];
        out[(size_t)i * 2]     = __floats2half2_rn(v.x, v.y);
        out[(size_t)i * 2 + 1] = __floats2half2_rn(v.z, v.w);
    }
}

// ---------------- RMSNorm: one block per row, float4 loads, fp16 out ----------
__global__ void __launch_bounds__(256) rmsnorm_k(const float* __restrict__ x,
                                                 const float* __restrict__ w,
                                                 __half* __restrict__ out, int Dm) {
    int row = blockIdx.x;
    const float4* xr4 = (const float4*)(x + (size_t)row * Dm);
    const float4* w4  = (const float4*)w;
    const int n4 = Dm / 4;
    float ss = 0.f;
    for (int i = threadIdx.x; i < n4; i += 256) {
        float4 v = xr4[i];
        ss += v.x * v.x + v.y * v.y + v.z * v.z + v.w * v.w;
    }
    __shared__ float red[256];
    red[threadIdx.x] = ss;
    __syncthreads();
    for (int s = 128; s > 0; s >>= 1) {
        if (threadIdx.x < s) red[threadIdx.x] += red[threadIdx.x + s];
        __syncthreads();
    }
    float rms = sqrtf(red[0] / (float)Dm);
    float inv = 1.0f / (rms + 1e-8f);
    __half2* orow = (__half2*)(out + (size_t)row * Dm);
    for (int i = threadIdx.x; i < n4; i += 256) {
        float4 v = xr4[i];
        float4 g4 = w4[i];
        orow[i * 2]     = __floats2half2_rn(g4.x * v.x * inv, g4.y * v.y * inv);
        orow[i * 2 + 1] = __floats2half2_rn(g4.z * v.z * inv, g4.w * v.w * inv);
    }
}

// ---------------- RoPE on packed QKV (in-place, fp16, half2-vectorized) -------
__global__ void __launch_bounds__(256) rope_qkv_k(__half* __restrict__ qkv,
                                                  const float* __restrict__ cs,
                                                  const float* __restrict__ sn) {
    int idx = blockIdx.x * 256 + threadIdx.x;
    int dp = (idx & 31) * 2;
    int head = (idx >> 5) & (N_HEADS - 1);
    int row = idx >> 9;
    if (row >= M_ROWS) return;
    int t = row & (T_SEQ - 1);
    float2 c1 = *(const float2*)(cs + t * HEAD_DIM + dp);
    float2 s1 = *(const float2*)(sn + t * HEAD_DIM + dp);
    float2 c2 = *(const float2*)(cs + t * HEAD_DIM + dp + 64);
    float2 s2 = *(const float2*)(sn + t * HEAD_DIM + dp + 64);
    size_t base = (size_t)row * QKV_STRIDE + head * HEAD_DIM;
    __half2* q0 = (__half2*)(qkv + base + dp);
    __half2* q1 = (__half2*)(qkv + base + dp + 64);
    __half2* k0 = (__half2*)(qkv + base + D_MODEL + dp);
    __half2* k1 = (__half2*)(qkv + base + D_MODEL + dp + 64);
    float2 qa = __half22float2(*q0), qb = __half22float2(*q1);
    *q0 = __floats2half2_rn(qa.x * c1.x - qb.x * s1.x, qa.y * c1.y - qb.y * s1.y);
    *q1 = __floats2half2_rn(qb.x * c2.x + qa.x * s2.x, qb.y * c2.y + qa.y * s2.y);
    float2 ka = __half22float2(*k0), kb = __half22float2(*k1);
    *k0 = __floats2half2_rn(ka.x * c1.x - kb.x * s1.x, ka.y * c1.y - kb.y * s1.y);
    *k1 = __floats2half2_rn(kb.x * c2.x + ka.x * s2.x, kb.y * c2.y + ka.y * s2.y);
}

// ---------------- Flash attention (R12-proven, 64-row Q tiles, 4 warps) -------
#define FROW_B 272
#define FBUF_B (64 * FROW_B)
#define FLASH_SMEM_BYTES (5 * FBUF_B)

__global__ void __launch_bounds__(128) flash_mma_k(const __half* __restrict__ QKV,
                                                   __half* __restrict__ O) {
    extern __shared__ char fsm[];
    const uint32_t sQ  = smem_u32(fsm);
    const uint32_t sK0 = sQ + FBUF_B, sV0 = sQ + 2 * FBUF_B;
    const uint32_t sK1 = sQ + 3 * FBUF_B, sV1 = sQ + 4 * FBUF_B;

    const int qt = (int)(gridDim.x - 1 - blockIdx.x);  // LPT order
    const int h = blockIdx.y, b = blockIdx.z;
    const int tid = threadIdx.x;
    const int w = tid >> 5, lane = tid & 31;
    const int g = lane >> 2, t = lane & 3;
    const int r8 = lane & 7, sel = lane >> 3;

    const size_t seq0 = (size_t)b * T_SEQ;
    const size_t col0 = (size_t)h * HEAD_DIM;
    const __half* Q = QKV + col0;
    const __half* K = QKV + col0 + D_MODEL;
    const __half* V = QKV + col0 + 2 * D_MODEL;

    const int lrow = tid >> 4;
    const int lc   = tid & 15;
    const size_t gOff = (size_t)lrow * QKV_STRIDE + lc * 8;
    const uint32_t sOff = (uint32_t)(lrow * FROW_B + lc * 16);

#define FLOAD(SBASE, GPTR) do { \
        const __half* _g = (GPTR) + gOff; \
        uint32_t _s = (SBASE) + sOff; \
        _Pragma("unroll") \
        for (int _i = 0; _i < 8; _i++) { \
            cp_async16(_s, _g); \
            _s += 8 * FROW_B; _g += (size_t)8 * QKV_STRIDE; \
        } \
    } while (0)

    FLOAD(sQ, Q + (seq0 + (size_t)qt * 64) * QKV_STRIDE);
    FLOAD(sK0, K + seq0 * QKV_STRIDE);
    FLOAD(sV0, V + seq0 * QKV_STRIDE);
    CP_COMMIT();
    CP_WAIT(0);
    __syncthreads();

    uint32_t qa[8][4];
    {
        uint32_t qbase = sQ + (uint32_t)((16 * w + r8 + 8 * (sel & 1)) * FROW_B + (sel >> 1) * 16);
#pragma unroll
        for (int u = 0; u < 8; u++)
            LDSM4(qa[u][0], qa[u][1], qa[u][2], qa[u][3], qbase + u * 32);
    }

    const uint32_t koff = (uint32_t)((r8 + 8 * (sel >> 1)) * FROW_B + (sel & 1) * 16);
    const uint32_t voff = (uint32_t)((8 * (sel & 1) + r8) * FROW_B + (sel >> 1) * 16);

    float oacc[16][4];
#pragma unroll
    for (int j = 0; j < 16; j++) { oacc[j][0] = 0; oacc[j][1] = 0; oacc[j][2] = 0; oacc[j][3] = 0; }
    float mA = -1e30f, mB = -1e30f, lA = 0.f, lB = 0.f;

    const int rowA = qt * 64 + 16 * w + g;
    const int rowB = rowA + 8;
    const float CEXP = ATTN_SCALE * 1.4426950408889634f;

    for (int kt = 0; kt <= qt; kt++) {
        const uint32_t sK = (kt & 1) ? sK1 : sK0;
        const uint32_t sV = (kt & 1) ? sV1 : sV0;
        const bool more = (kt + 1) <= qt;
        if (more) {
            const uint32_t nK = (kt & 1) ? sK0 : sK1;
            const uint32_t nV = (kt & 1) ? sV0 : sV1;
            FLOAD(nK, K + (seq0 + (size_t)(kt + 1) * 64) * QKV_STRIDE);
            FLOAD(nV, V + (seq0 + (size_t)(kt + 1) * 64) * QKV_STRIDE);
            CP_COMMIT();
        }
        if (kt > 0) {
            if (more) { CP_WAIT(1); } else { CP_WAIT(0); }
            __syncthreads();
        }

        float sacc[8][4];
#pragma unroll
        for (int j = 0; j < 8; j++) { sacc[j][0] = 0; sacc[j][1] = 0; sacc[j][2] = 0; sacc[j][3] = 0; }
#pragma unroll
        for (int u = 0; u < 8; u++) {
#pragma unroll
            for (int jp = 0; jp < 4; jp++) {
                uint32_t k0, k1, k2, k3;
                LDSM4(k0, k1, k2, k3, sK + koff + jp * (16 * FROW_B) + u * 32);
                mma_f16(sacc[2 * jp],     qa[u][0], qa[u][1], qa[u][2], qa[u][3], k0, k1);
                mma_f16(sacc[2 * jp + 1], qa[u][0], qa[u][1], qa[u][2], qa[u][3], k2, k3);
            }
        }

        if (kt == qt) {
#pragma unroll
            for (int j = 0; j < 8; j++) {
                int c0 = kt * 64 + 8 * j + 2 * t;
                if (c0     > rowA) sacc[j][0] = -1e30f;
                if (c0 + 1 > rowA) sacc[j][1] = -1e30f;
                if (c0     > rowB) sacc[j][2] = -1e30f;
                if (c0 + 1 > rowB) sacc[j][3] = -1e30f;
            }
        }

        float mxA = -1e30f, mxB = -1e30f;
#pragma unroll
        for (int j = 0; j < 8; j++) {
            mxA = fmaxf(mxA, fmaxf(sacc[j][0], sacc[j][1]));
            mxB = fmaxf(mxB, fmaxf(sacc[j][2], sacc[j][3]));
        }
        mxA = fmaxf(mxA, __shfl_xor_sync(0xffffffffu, mxA, 1));
        mxA = fmaxf(mxA, __shfl_xor_sync(0xffffffffu, mxA, 2));
        mxB = fmaxf(mxB, __shfl_xor_sync(0xffffffffu, mxB, 1));
        mxB = fmaxf(mxB, __shfl_xor_sync(0xffffffffu, mxB, 2));
        float mnA = fmaxf(mA, mxA), mnB = fmaxf(mB, mxB);
        float aA = exp2f((mA - mnA) * CEXP), aB = exp2f((mB - mnB) * CEXP);
        mA = mnA; mB = mnB;

        uint32_t ph[8][2];
        float sA = 0.f, sB = 0.f;
#pragma unroll
        for (int j = 0; j < 8; j++) {
            float p0 = exp2f((sacc[j][0] - mnA) * CEXP);
            float p1 = exp2f((sacc[j][1] - mnA) * CEXP);
            float p2 = exp2f((sacc[j][2] - mnB) * CEXP);
            float p3 = exp2f((sacc[j][3] - mnB) * CEXP);
            __half2 h01 = __floats2half2_rn(p0, p1);
            __half2 h23 = __floats2half2_rn(p2, p3);
            ph[j][0] = *(uint32_t*)&h01;
            ph[j][1] = *(uint32_t*)&h23;
            float2 f01 = __half22float2(h01);
            float2 f23 = __half22float2(h23);
            sA += f01.x + f01.y;
            sB += f23.x + f23.y;
        }
        sA += __shfl_xor_sync(0xffffffffu, sA, 1);
        sA += __shfl_xor_sync(0xffffffffu, sA, 2);
        sB += __shfl_xor_sync(0xffffffffu, sB, 1);
        sB += __shfl_xor_sync(0xffffffffu, sB, 2);
        lA = lA * aA + sA;
        lB = lB * aB + sB;

#pragma unroll
        for (int j = 0; j < 16; j++) {
            oacc[j][0] *= aA; oacc[j][1] *= aA;
            oacc[j][2] *= aB; oacc[j][3] *= aB;
        }

#pragma unroll
        for (int uk = 0; uk < 4; uk++) {
            uint32_t a0 = ph[2 * uk][0], a1 = ph[2 * uk][1];
            uint32_t a2 = ph[2 * uk + 1][0], a3 = ph[2 * uk + 1][1];
#pragma unroll
            for (int jp = 0; jp < 8; jp++) {
                uint32_t v0, v1, v2, v3;
                LDSM4T(v0, v1, v2, v3, sV + voff + uk * (16 * FROW_B) + jp * 32);
                mma_f16(oacc[2 * jp],     a0, a1, a2, a3, v0, v1);
                mma_f16(oacc[2 * jp + 1], a0, a1, a2, a3, v2, v3);
            }
        }
        __syncthreads();
    }
#undef FLOAD

    float iA = 1.f / lA, iB = 1.f / lB;
    __half* orA = O + (seq0 + rowA) * D_MODEL + col0 + 2 * t;
    __half* orB = O + (seq0 + rowB) * D_MODEL + col0 + 2 * t;
#pragma unroll
    for (int j = 0; j < 16; j++) {
        __half2 hA = __floats2half2_rn(oacc[j][0] * iA, oacc[j][1] * iA);
        __half2 hB = __floats2half2_rn(oacc[j][2] * iB, oacc[j][3] * iB);
        *(__half2*)(orA + 8 * j) = hA;
        *(__half2*)(orB + 8 * j) = hB;
    }
}

// ---------------- launch ----------------
extern "C" void kernel_launch(void* const* d_in, const int* in_sizes, int n_in,
                              void* d_out, int out_size) {
    const float* x    = (const float*)d_in[0];
    const float* cs   = (const float*)d_in[1];
    const float* sn   = (const float*)d_in[2];
    const float* g1   = (const float*)d_in[4];
    const float* g2   = (const float*)d_in[5];
    const float* Wq   = (const float*)d_in[6];
    const float* Wk   = (const float*)d_in[7];
    const float* Wv   = (const float*)d_in[8];
    const float* Wo   = (const float*)d_in[9];
    const float* W1   = (const float*)d_in[10];
    const float* W2   = (const float*)d_in[11];
    const float* Wout = (const float*)d_in[12];
    float* out = (float*)d_out;

    __half *ph, *pqkv, *pa, *ph2, *pf2h, *pw;
    float *px2;
    cudaGetSymbolAddress((void**)&ph,   g_h);
    cudaGetSymbolAddress((void**)&pqkv, g_qkv);
    cudaGetSymbolAddress((void**)&pa,   g_a);
    cudaGetSymbolAddress((void**)&px2,  g_x2);
    cudaGetSymbolAddress((void**)&ph2,  g_h2);
    cudaGetSymbolAddress((void**)&pf2h, g_f2h);
    cudaGetSymbolAddress((void**)&pw,   g_wbuf);

    cudaFuncSetAttribute(gemm_f16, cudaFuncAttributeMaxDynamicSharedMemorySize,
                         GEMM64_SMEM);
    cudaFuncSetAttribute(gemm_f16_ff, cudaFuncAttributeMaxDynamicSharedMemorySize,
                         GEMM64_SMEM);
    cudaFuncSetAttribute(flash_mma_k, cudaFuncAttributeMaxDynamicSharedMemorySize,
                         FLASH_SMEM_BYTES);

    // 0) fused weight conversion (1 launch, MLP=4)
    tohalf_all_k<<<(CONV_TOTAL + 1023) / 1024, 256>>>(
        (const float4*)Wq, (const float4*)Wk, (const float4*)Wv, (const float4*)Wo,
        (const float4*)W1, (const float4*)W2, (const float4*)Wout, (__half2*)pw);

    // 1) h = rmsnorm(x, g1)  (fp16 out)
    rmsnorm_k<<<M_ROWS, 256>>>(x, g1, ph, D_MODEL);

    // 2) fused QKV projection: [M,6144] = h @ [Wq;Wk;Wv]^T  (BK=64)
    dim3 gqkv(QKV_STRIDE / 128, M_ROWS / 128);
    gemm_f16<<<gqkv, 256, GEMM64_SMEM>>>(ph, pw + O_WQ, nullptr, nullptr, pqkv,
                                         QKV_STRIDE, D_MODEL);

    // 3) RoPE on packed QKV (half2-vectorized)
    rope_qkv_k<<<(M_ROWS * N_HEADS * 32) / 256, 256>>>(pqkv, cs, sn);

    // 4) causal flash attention (64-row Q tiles) -> fp16
    dim3 gattn(T_SEQ / 64, N_HEADS, B_SZ);
    flash_mma_k<<<gattn, 128, FLASH_SMEM_BYTES>>>(pqkv, pa);

    // 5) x2 = x + attn @ Wo^T  (BK=64)
    dim3 gproj(D_MODEL / 128, M_ROWS / 128);
    gemm_f16<<<gproj, 256, GEMM64_SMEM>>>(pa, pw + O_WO, x, px2, nullptr,
                                          D_MODEL, D_MODEL);

    // 6) h2 = rmsnorm(x2, g2)
    rmsnorm_k<<<M_ROWS, 256>>>(px2, g2, ph2, D_MODEL);

    // 7) merged FF (BK=64): f2h = silu(h2@W1^T) * (h2@W2^T), gate staged in f2h
    dim3 gff(D_FF / 128, M_ROWS / 128);
    gemm_f16_ff<<<gff, 256, GEMM64_SMEM>>>(ph2, pw + O_W1, pw + O_W2, pf2h,
                                           D_FF, D_MODEL);

    // 8) out = x2 + f2h @ Wout^T  (BK=64, Ki=5504 -> 86 tiles)
    gemm_f16<<<gproj, 256, GEMM64_SMEM>>>(pf2h, pw + O_WOUT, px2, out, nullptr,
                                          D_MODEL, D_FF);
}